// round 10
// baseline (speedup 1.0000x reference)
#include <cuda_runtime.h>
#include <cstdint>

#define NC 1024
#define DY 16
#define G  256
#define M  2
#define CH 64
#define NT 16          // tiles per dim (G/16)
#define S  2           // split-K segments
#define XTOT (M * G * G * 2)
#define ZTOT (M * G * G * 17)

typedef unsigned long long u64;

// TRANSPOSED axis weights: g_W[axis][m][c][i]  (i contiguous)
__device__ float g_W[2][M][NC][G];            // 4 MB
__device__ int   g_len[M][NT][NT];
__device__ int   g_list[M][NT][NT][NC];       // 2 MB
__device__ float g_part[S][ZTOT];             // 17.8 MB (L2-resident)

// ---- packed f32x2 helpers ----
__device__ __forceinline__ u64 pack2(float lo, float hi) {
    u64 r; asm("mov.b64 %0, {%1, %2};" : "=l"(r) : "f"(lo), "f"(hi)); return r;
}
__device__ __forceinline__ void unpack2(float& lo, float& hi, u64 v) {
    asm("mov.b64 {%0, %1}, %2;" : "=f"(lo), "=f"(hi) : "l"(v));
}
__device__ __forceinline__ void ffma2(u64& d, u64 a, u64 b) {
    asm("fma.rn.f32x2 %0, %1, %2, %0;" : "+l"(d) : "l"(a), "l"(b));
}
__device__ __forceinline__ void lds_v2_f32(float& a, float& b, uint32_t addr) {
    asm volatile("ld.shared.v2.f32 {%0, %1}, [%2];" : "=f"(a), "=f"(b) : "r"(addr));
}
__device__ __forceinline__ void cpasync16(uint32_t dst, const void* src, int src_bytes) {
    asm volatile("cp.async.cg.shared.global [%0], [%1], 16, %2;"
                 :: "r"(dst), "l"(src), "r"(src_bytes));
}
__device__ __forceinline__ void cpasync_commit() {
    asm volatile("cp.async.commit_group;");
}
template <int N>
__device__ __forceinline__ void cpasync_wait() {
    asm volatile("cp.async.wait_group %0;" :: "n"(N));
}

// ---------------------------------------------------------------------------
// Kernel 1: build Wx/Wy transposed. Warp-uniform skip of far entries
// (t^2 > 27.63 -> w = 0, same cutoff as compaction) avoids ~72% of MUFUs.
// ---------------------------------------------------------------------------
__global__ void weights_kernel(const float* __restrict__ xc,
                               const float* __restrict__ lsp) {
    int idx = blockIdx.x * blockDim.x + threadIdx.x;   // 1,048,576
    int i = idx & (G - 1);
    int c = (idx >> 8) & (NC - 1);
    int d = (idx >> 18) & 1;
    int m = idx >> 19;
    float l = 1e-5f + log1pf(expf(lsp[d]));            // exact softplus
    float rl = 1.0f / l;
    float g = 1.0f + (float)(i - 128) * (1.0f / 64.0f);
    float x = xc[(m * NC + c) * 2 + d];
    float t = (g - x) * rl;
    float t2 = t * t;
    float w = 0.0f;
    bool keep = t2 <= 27.63f;
    if (__any_sync(0xffffffffu, keep)) {
        if (keep) w = __expf(-0.5f * t2);
    }
    g_W[d][m][c][i] = w;
}

// ---------------------------------------------------------------------------
// Kernel 2: per-tile c-list compaction (one warp per 16x16 tile, deterministic)
// ---------------------------------------------------------------------------
__global__ void compact_kernel(const float* __restrict__ xc,
                               const float* __restrict__ lsp) {
    int warp = (blockIdx.x * blockDim.x + threadIdx.x) >> 5;
    int lane = threadIdx.x & 31;
    if (warp >= M * NT * NT) return;
    int jT = warp & (NT - 1);
    int iT = (warp >> 4) & (NT - 1);
    int m  = warp >> 8;

    float rlx = 1.0f / (1e-5f + log1pf(expf(lsp[0])));
    float rly = 1.0f / (1e-5f + log1pf(expf(lsp[1])));
    float x0 = 1.0f + (float)(iT * 16 - 128) * (1.0f / 64.0f);
    float x1 = x0 + 15.0f / 64.0f;
    float y0 = 1.0f + (float)(jT * 16 - 128) * (1.0f / 64.0f);
    float y1 = y0 + 15.0f / 64.0f;
    const float thr = 27.63f;   // weight cutoff ~1e-6

    int count = 0;
    int* lst = g_list[m][iT][jT];
    for (int c0 = 0; c0 < NC; c0 += 32) {
        int c = c0 + lane;
        float cx = xc[(m * NC + c) * 2 + 0];
        float cy = xc[(m * NC + c) * 2 + 1];
        float dx = fmaxf(fmaxf(x0 - cx, cx - x1), 0.0f) * rlx;
        float dy = fmaxf(fmaxf(y0 - cy, cy - y1), 0.0f) * rly;
        bool keep = (dx * dx + dy * dy) <= thr;
        unsigned mask = __ballot_sync(0xffffffffu, keep);
        int off = __popc(mask & ((1u << lane) - 1u));
        if (keep) lst[count + off] = c;
        count += __popc(mask);
    }
    if (lane == 0) g_len[m][iT][jT] = count;
}

// ---------------------------------------------------------------------------
// Kernel 3: split-K register-blocked contraction (2i x 2j x 4k per thread),
// cp.async double-buffered. grid = (NT, NT, M*S); s = z&1, m = z>>1.
// Segment s handles list entries [s*half, min((s+1)*half, len)).
// ---------------------------------------------------------------------------
__global__ __launch_bounds__(256, 3)
void setconv_partial(const float* __restrict__ yc) {
    __shared__ float  wxs[2][CH][16];   // [buf][c][i]
    __shared__ float  wys[2][CH][16];   // [buf][c][j]
    __shared__ float4 ycs[2][CH][4];    // [buf][c][k/4]

    const int zid = blockIdx.z;
    const int s  = zid & (S - 1);
    const int m  = zid >> 1;
    const int iT = blockIdx.y;
    const int jT = blockIdx.x;
    const int tid = threadIdx.x;
    const int tj2 = tid & 7;
    const int ti2 = (tid >> 3) & 7;
    const int tk  = tid >> 6;           // 0..3, uniform per warp-pair
    const int iBase = iT * 16;
    const int jBase = jT * 16;

    const int len = g_len[m][iT][jT];
    const int half = (len + 1) >> 1;
    const int lo = s * half;
    const int hi = min(lo + half, len);
    const int nchunk = (hi > lo) ? ((hi - lo + CH - 1) / CH) : 0;

    const int* __restrict__ lst = g_list[m][iT][jT];
    const float4* __restrict__ yc4 = (const float4*)yc;

    // staging: cc = tid>>2, q = tid&3 (16B units)
    const int scc = tid >> 2;
    const int sq  = tid & 3;
    const uint32_t wxs_s = (uint32_t)__cvta_generic_to_shared(&wxs[0][0][0]);
    const uint32_t wys_s = (uint32_t)__cvta_generic_to_shared(&wys[0][0][0]);
    const uint32_t ycs_s = (uint32_t)__cvta_generic_to_shared(&ycs[0][0][0]);
    const uint32_t sdoff = (uint32_t)(scc * 16 + sq * 4) * 4;

    auto stage = [&](int buf, int c0) {
        int cpos = c0 + scc;
        bool valid = cpos < hi;
        int cidx = valid ? lst[cpos] : 0;
        int b16 = valid ? 16 : 0;
        uint32_t boff = (uint32_t)buf * (CH * 16 * 4);
        cpasync16(wxs_s + boff + sdoff, &g_W[0][m][cidx][iBase + sq * 4], b16);
        cpasync16(wys_s + boff + sdoff, &g_W[1][m][cidx][jBase + sq * 4], b16);
        cpasync16(ycs_s + boff + sdoff, &yc4[((m * NC + cidx) << 2) + sq], b16);
        cpasync_commit();
    };

    u64 acc2[4][2];
#pragma unroll
    for (int a = 0; a < 4; a++) { acc2[a][0] = 0ull; acc2[a][1] = 0ull; }
    float accD[4] = {0.0f, 0.0f, 0.0f, 0.0f};

    if (nchunk > 0) {
        stage(0, lo);
        for (int t = 0; t < nchunk; t++) {
            int cur = t & 1;
            if (t + 1 < nchunk) {
                stage(cur ^ 1, lo + (t + 1) * CH);
                cpasync_wait<1>();
            } else {
                cpasync_wait<0>();
            }
            __syncthreads();

            const uint32_t bo = (uint32_t)cur * (CH * 16 * 4);
            const uint32_t wx_a = wxs_s + bo + (uint32_t)ti2 * 8;
            const uint32_t wy_a = wys_s + bo + (uint32_t)tj2 * 8;
            const uint32_t yc_a = ycs_s + bo + (uint32_t)tk * 16;

            if (tk == 3) {
#pragma unroll 8
                for (int cc = 0; cc < CH; ++cc) {
                    float wx0, wx1, wy0, wy1;
                    lds_v2_f32(wx0, wx1, wx_a + cc * 64);
                    lds_v2_f32(wy0, wy1, wy_a + cc * 64);
                    u64 y01, y23;
                    asm volatile("ld.shared.v2.b64 {%0, %1}, [%2];"
                                 : "=l"(y01), "=l"(y23) : "r"(yc_a + cc * 64));
                    float w00 = wx0 * wy0, w01 = wx0 * wy1;
                    float w10 = wx1 * wy0, w11 = wx1 * wy1;
                    accD[0] += w00; accD[1] += w01; accD[2] += w10; accD[3] += w11;
                    u64 p00 = pack2(w00, w00), p01 = pack2(w01, w01);
                    u64 p10 = pack2(w10, w10), p11 = pack2(w11, w11);
                    ffma2(acc2[0][0], p00, y01); ffma2(acc2[0][1], p00, y23);
                    ffma2(acc2[1][0], p01, y01); ffma2(acc2[1][1], p01, y23);
                    ffma2(acc2[2][0], p10, y01); ffma2(acc2[2][1], p10, y23);
                    ffma2(acc2[3][0], p11, y01); ffma2(acc2[3][1], p11, y23);
                }
            } else {
#pragma unroll 8
                for (int cc = 0; cc < CH; ++cc) {
                    float wx0, wx1, wy0, wy1;
                    lds_v2_f32(wx0, wx1, wx_a + cc * 64);
                    lds_v2_f32(wy0, wy1, wy_a + cc * 64);
                    u64 y01, y23;
                    asm volatile("ld.shared.v2.b64 {%0, %1}, [%2];"
                                 : "=l"(y01), "=l"(y23) : "r"(yc_a + cc * 64));
                    float w00 = wx0 * wy0, w01 = wx0 * wy1;
                    float w10 = wx1 * wy0, w11 = wx1 * wy1;
                    u64 p00 = pack2(w00, w00), p01 = pack2(w01, w01);
                    u64 p10 = pack2(w10, w10), p11 = pack2(w11, w11);
                    ffma2(acc2[0][0], p00, y01); ffma2(acc2[0][1], p00, y23);
                    ffma2(acc2[1][0], p01, y01); ffma2(acc2[1][1], p01, y23);
                    ffma2(acc2[2][0], p10, y01); ffma2(acc2[2][1], p10, y23);
                    ffma2(acc2[3][0], p11, y01); ffma2(acc2[3][1], p11, y23);
                }
            }
            __syncthreads();
        }
    }

    // --- write partials (always, buffer is uninitialized) ---
#pragma unroll
    for (int di = 0; di < 2; di++) {
#pragma unroll
        for (int dj = 0; dj < 2; dj++) {
            int ij = di * 2 + dj;
            int i = iBase + ti2 * 2 + di;
            int j = jBase + tj2 * 2 + dj;
            float* po = &g_part[s][((size_t)((m * G + i) * G + j)) * 17 + tk * 4];
            float a0, a1, a2, a3;
            unpack2(a0, a1, acc2[ij][0]);
            unpack2(a2, a3, acc2[ij][1]);
            po[0] = a0; po[1] = a1; po[2] = a2; po[3] = a3;
            if (tk == 3) po[4] = accD[ij];
        }
    }
}

// ---------------------------------------------------------------------------
// Kernel 4: finalize — x_grid coords + fixed-order sum of S partials.
// ---------------------------------------------------------------------------
__global__ void finalize_kernel(float* __restrict__ out) {
    int idx = blockIdx.x * blockDim.x + threadIdx.x;   // 2,490,368 total
    if (idx < XTOT) {
        int d = idx & 1;
        int j = (idx >> 1) & (G - 1);
        int i = (idx >> 9) & (G - 1);
        int v = d ? j : i;
        out[idx] = 1.0f + (float)(v - 128) * (1.0f / 64.0f);
    } else {
        int e = idx - XTOT;
        out[idx] = g_part[0][e] + g_part[1][e];
    }
}

// ---------------------------------------------------------------------------
extern "C" void kernel_launch(void* const* d_in, const int* in_sizes, int n_in,
                              void* d_out, int out_size) {
    const float* xc  = (const float*)d_in[0];  // [2,1024,2]
    const float* yc  = (const float*)d_in[1];  // [2,1024,16]
    const float* lsp = (const float*)d_in[3];  // [2]
    float* out = (float*)d_out;

    weights_kernel<<<(M * 2 * G * NC) / 256, 256>>>(xc, lsp);
    compact_kernel<<<(M * NT * NT * 32) / 256, 256>>>(xc, lsp);
    dim3 g(NT, NT, M * S);
    setconv_partial<<<g, 256>>>(yc);
    finalize_kernel<<<(XTOT + ZTOT) / 256, 256>>>(out);
}

// round 11
// speedup vs baseline: 1.0316x; 1.0316x over previous
#include <cuda_runtime.h>
#include <cstdint>

#define NC 1024
#define DY 16
#define G  256
#define M  2
#define CH 64
#define NT 16          // tiles per dim (G/16)
#define NTILES (M * NT * NT)   // 512
#define XTOT (M * G * G * 2)

typedef unsigned long long u64;

// TRANSPOSED axis weights: g_W[axis][m][c][i]  (i contiguous)
__device__ float g_W[2][M][NC][G];            // 4 MB
__device__ int   g_len[M][NT][NT];
__device__ int   g_list[M][NT][NT][NC];       // 2 MB
__device__ int   g_order[NTILES];             // heavy-first tile order

// ---- packed f32x2 helpers ----
__device__ __forceinline__ u64 pack2(float lo, float hi) {
    u64 r; asm("mov.b64 %0, {%1, %2};" : "=l"(r) : "f"(lo), "f"(hi)); return r;
}
__device__ __forceinline__ void unpack2(float& lo, float& hi, u64 v) {
    asm("mov.b64 {%0, %1}, %2;" : "=f"(lo), "=f"(hi) : "l"(v));
}
__device__ __forceinline__ void ffma2(u64& d, u64 a, u64 b) {
    asm("fma.rn.f32x2 %0, %1, %2, %0;" : "+l"(d) : "l"(a), "l"(b));
}
__device__ __forceinline__ void lds_v2_f32(float& a, float& b, uint32_t addr) {
    asm volatile("ld.shared.v2.f32 {%0, %1}, [%2];" : "=f"(a), "=f"(b) : "r"(addr));
}
__device__ __forceinline__ void cpasync16(uint32_t dst, const void* src, int src_bytes) {
    asm volatile("cp.async.cg.shared.global [%0], [%1], 16, %2;"
                 :: "r"(dst), "l"(src), "r"(src_bytes));
}
__device__ __forceinline__ void cpasync_commit() {
    asm volatile("cp.async.commit_group;");
}
template <int N>
__device__ __forceinline__ void cpasync_wait() {
    asm volatile("cp.async.wait_group %0;" :: "n"(N));
}

// ---------------------------------------------------------------------------
// Kernel 1: build Wx/Wy transposed; warp-uniform MUFU skip for far entries
// (t^2 > 27.63 -> w = 0; same cutoff as compaction, so consistent)
// ---------------------------------------------------------------------------
__global__ void weights_kernel(const float* __restrict__ xc,
                               const float* __restrict__ lsp) {
    int idx = blockIdx.x * blockDim.x + threadIdx.x;   // 1,048,576
    int i = idx & (G - 1);
    int c = (idx >> 8) & (NC - 1);
    int d = (idx >> 18) & 1;
    int m = idx >> 19;
    float l = 1e-5f + log1pf(expf(lsp[d]));            // exact softplus
    float rl = 1.0f / l;
    float g = 1.0f + (float)(i - 128) * (1.0f / 64.0f);
    float x = xc[(m * NC + c) * 2 + d];
    float t = (g - x) * rl;
    float t2 = t * t;
    float w = 0.0f;
    bool keep = t2 <= 27.63f;
    if (__any_sync(0xffffffffu, keep)) {
        if (keep) w = __expf(-0.5f * t2);
    }
    g_W[d][m][c][i] = w;
}

// ---------------------------------------------------------------------------
// Kernel 2: per-tile c-list compaction (one warp per 16x16 tile, deterministic)
// ---------------------------------------------------------------------------
__global__ void compact_kernel(const float* __restrict__ xc,
                               const float* __restrict__ lsp) {
    int warp = (blockIdx.x * blockDim.x + threadIdx.x) >> 5;
    int lane = threadIdx.x & 31;
    if (warp >= NTILES) return;
    int jT = warp & (NT - 1);
    int iT = (warp >> 4) & (NT - 1);
    int m  = warp >> 8;

    float rlx = 1.0f / (1e-5f + log1pf(expf(lsp[0])));
    float rly = 1.0f / (1e-5f + log1pf(expf(lsp[1])));
    float x0 = 1.0f + (float)(iT * 16 - 128) * (1.0f / 64.0f);
    float x1 = x0 + 15.0f / 64.0f;
    float y0 = 1.0f + (float)(jT * 16 - 128) * (1.0f / 64.0f);
    float y1 = y0 + 15.0f / 64.0f;
    const float thr = 27.63f;   // weight cutoff ~1e-6

    int count = 0;
    int* lst = g_list[m][iT][jT];
    for (int c0 = 0; c0 < NC; c0 += 32) {
        int c = c0 + lane;
        float cx = xc[(m * NC + c) * 2 + 0];
        float cy = xc[(m * NC + c) * 2 + 1];
        float dx = fmaxf(fmaxf(x0 - cx, cx - x1), 0.0f) * rlx;
        float dy = fmaxf(fmaxf(y0 - cy, cy - y1), 0.0f) * rly;
        bool keep = (dx * dx + dy * dy) <= thr;
        unsigned mask = __ballot_sync(0xffffffffu, keep);
        int off = __popc(mask & ((1u << lane) - 1u));
        if (keep) lst[count + off] = c;
        count += __popc(mask);
    }
    if (lane == 0) g_len[m][iT][jT] = count;
}

// ---------------------------------------------------------------------------
// Kernel 3: deterministic heavy-first rank (1 CTA, 512 threads)
// rank = #{u : len[u] > len[t]  or  (len[u]==len[t] and u < t)}
// ---------------------------------------------------------------------------
__global__ void order_kernel() {
    __shared__ int sl[NTILES];
    int t = threadIdx.x;
    const int* lenf = (const int*)g_len;
    sl[t] = lenf[t];
    __syncthreads();
    int mylen = sl[t];
    int rank = 0;
#pragma unroll 8
    for (int u = 0; u < NTILES; u++) {
        int ul = sl[u];
        rank += (ul > mylen) || (ul == mylen && u < t);
    }
    g_order[rank] = t;
}

// ---------------------------------------------------------------------------
// Kernel 4: register-blocked contraction (2i x 2j x 4k per thread),
// cp.async double-buffered, heavy-first tile order, grid coords folded in.
// ---------------------------------------------------------------------------
__global__ __launch_bounds__(256, 4)
void setconv_kernel(const float* __restrict__ yc, float* __restrict__ out) {
    __shared__ float  wxs[2][CH][16];   // [buf][c][i]
    __shared__ float  wys[2][CH][16];   // [buf][c][j]
    __shared__ float4 ycs[2][CH][4];    // [buf][c][k/4]

    const int tile = g_order[blockIdx.x];
    const int jT = tile & (NT - 1);
    const int iT = (tile >> 4) & (NT - 1);
    const int m  = tile >> 8;
    const int tid = threadIdx.x;
    const int tj2 = tid & 7;
    const int ti2 = (tid >> 3) & 7;
    const int tk  = tid >> 6;           // 0..3, uniform per warp-pair
    const int iBase = iT * 16;
    const int jBase = jT * 16;

    // x_grid_b coords for this tile (tk==0 quarter of threads: 4 positions each)
    if (tk == 0) {
#pragma unroll
        for (int di = 0; di < 2; di++) {
#pragma unroll
            for (int dj = 0; dj < 2; dj++) {
                int i = iBase + ti2 * 2 + di;
                int j = jBase + tj2 * 2 + dj;
                float2 g2;
                g2.x = 1.0f + (float)(i - 128) * (1.0f / 64.0f);
                g2.y = 1.0f + (float)(j - 128) * (1.0f / 64.0f);
                ((float2*)out)[(size_t)(m * G + i) * G + j] = g2;
            }
        }
    }

    const int len = g_len[m][iT][jT];
    const int* __restrict__ lst = g_list[m][iT][jT];
    const float4* __restrict__ yc4 = (const float4*)yc;

    // staging: cc = tid>>2, q = tid&3 (16B units)
    const int scc = tid >> 2;
    const int sq  = tid & 3;
    const uint32_t wxs_s = (uint32_t)__cvta_generic_to_shared(&wxs[0][0][0]);
    const uint32_t wys_s = (uint32_t)__cvta_generic_to_shared(&wys[0][0][0]);
    const uint32_t ycs_s = (uint32_t)__cvta_generic_to_shared(&ycs[0][0][0]);
    const uint32_t sdoff = (uint32_t)(scc * 16 + sq * 4) * 4;

    const int nchunk = (len + CH - 1) / CH;

    auto stage = [&](int buf, int c0) {
        int cpos = c0 + scc;
        bool valid = cpos < len;
        int cidx = valid ? lst[cpos] : 0;
        int b16 = valid ? 16 : 0;
        uint32_t boff = (uint32_t)buf * (CH * 16 * 4);
        cpasync16(wxs_s + boff + sdoff, &g_W[0][m][cidx][iBase + sq * 4], b16);
        cpasync16(wys_s + boff + sdoff, &g_W[1][m][cidx][jBase + sq * 4], b16);
        cpasync16(ycs_s + boff + sdoff, &yc4[((m * NC + cidx) << 2) + sq], b16);
        cpasync_commit();
    };

    u64 acc2[4][2];
#pragma unroll
    for (int a = 0; a < 4; a++) { acc2[a][0] = 0ull; acc2[a][1] = 0ull; }
    float accD[4] = {0.0f, 0.0f, 0.0f, 0.0f};

    if (nchunk > 0) {
        stage(0, 0);
        for (int t = 0; t < nchunk; t++) {
            int cur = t & 1;
            if (t + 1 < nchunk) {
                stage(cur ^ 1, (t + 1) * CH);
                cpasync_wait<1>();
            } else {
                cpasync_wait<0>();
            }
            __syncthreads();

            const uint32_t bo = (uint32_t)cur * (CH * 16 * 4);
            const uint32_t wx_a = wxs_s + bo + (uint32_t)ti2 * 8;
            const uint32_t wy_a = wys_s + bo + (uint32_t)tj2 * 8;
            const uint32_t yc_a = ycs_s + bo + (uint32_t)tk * 16;

            if (tk == 3) {
#pragma unroll 8
                for (int cc = 0; cc < CH; ++cc) {
                    float wx0, wx1, wy0, wy1;
                    lds_v2_f32(wx0, wx1, wx_a + cc * 64);
                    lds_v2_f32(wy0, wy1, wy_a + cc * 64);
                    u64 y01, y23;
                    asm volatile("ld.shared.v2.b64 {%0, %1}, [%2];"
                                 : "=l"(y01), "=l"(y23) : "r"(yc_a + cc * 64));
                    float w00 = wx0 * wy0, w01 = wx0 * wy1;
                    float w10 = wx1 * wy0, w11 = wx1 * wy1;
                    accD[0] += w00; accD[1] += w01; accD[2] += w10; accD[3] += w11;
                    u64 p00 = pack2(w00, w00), p01 = pack2(w01, w01);
                    u64 p10 = pack2(w10, w10), p11 = pack2(w11, w11);
                    ffma2(acc2[0][0], p00, y01); ffma2(acc2[0][1], p00, y23);
                    ffma2(acc2[1][0], p01, y01); ffma2(acc2[1][1], p01, y23);
                    ffma2(acc2[2][0], p10, y01); ffma2(acc2[2][1], p10, y23);
                    ffma2(acc2[3][0], p11, y01); ffma2(acc2[3][1], p11, y23);
                }
            } else {
#pragma unroll 8
                for (int cc = 0; cc < CH; ++cc) {
                    float wx0, wx1, wy0, wy1;
                    lds_v2_f32(wx0, wx1, wx_a + cc * 64);
                    lds_v2_f32(wy0, wy1, wy_a + cc * 64);
                    u64 y01, y23;
                    asm volatile("ld.shared.v2.b64 {%0, %1}, [%2];"
                                 : "=l"(y01), "=l"(y23) : "r"(yc_a + cc * 64));
                    float w00 = wx0 * wy0, w01 = wx0 * wy1;
                    float w10 = wx1 * wy0, w11 = wx1 * wy1;
                    u64 p00 = pack2(w00, w00), p01 = pack2(w01, w01);
                    u64 p10 = pack2(w10, w10), p11 = pack2(w11, w11);
                    ffma2(acc2[0][0], p00, y01); ffma2(acc2[0][1], p00, y23);
                    ffma2(acc2[1][0], p01, y01); ffma2(acc2[1][1], p01, y23);
                    ffma2(acc2[2][0], p10, y01); ffma2(acc2[2][1], p10, y23);
                    ffma2(acc2[3][0], p11, y01); ffma2(acc2[3][1], p11, y23);
                }
            }
            __syncthreads();
        }
    }

    // --- epilogue: 4 positions x 4 channels (+density for tk==3) ---
    float* outZ = out + (size_t)XTOT;
#pragma unroll
    for (int di = 0; di < 2; di++) {
#pragma unroll
        for (int dj = 0; dj < 2; dj++) {
            int ij = di * 2 + dj;
            int i = iBase + ti2 * 2 + di;
            int j = jBase + tj2 * 2 + dj;
            float* zo = outZ + ((size_t)((m * G + i) * G + j)) * 17 + tk * 4;
            float a0, a1, a2, a3;
            unpack2(a0, a1, acc2[ij][0]);
            unpack2(a2, a3, acc2[ij][1]);
            zo[0] = a0; zo[1] = a1; zo[2] = a2; zo[3] = a3;
            if (tk == 3) zo[4] = accD[ij];
        }
    }
}

// ---------------------------------------------------------------------------
extern "C" void kernel_launch(void* const* d_in, const int* in_sizes, int n_in,
                              void* d_out, int out_size) {
    const float* xc  = (const float*)d_in[0];  // [2,1024,2]
    const float* yc  = (const float*)d_in[1];  // [2,1024,16]
    const float* lsp = (const float*)d_in[3];  // [2]
    float* out = (float*)d_out;

    weights_kernel<<<(M * 2 * G * NC) / 256, 256>>>(xc, lsp);
    compact_kernel<<<(NTILES * 32) / 256, 256>>>(xc, lsp);
    order_kernel<<<1, NTILES>>>();
    setconv_kernel<<<NTILES, 256>>>(yc, out);
}